// round 9
// baseline (speedup 1.0000x reference)
#include <cuda_runtime.h>
#include <cuda_fp16.h>
#include <math.h>
#include <stdint.h>

#define BB 4
#define LL 4096
#define DD 1024
#define DI_ 4096
#define MM 8
#define ROWS (BB*LL)          /* 16384 */
#define THRG 0.5f
#define EPSLN 1e-6f

/* ---------------- scratch (device globals; no allocations allowed) -------- */
__device__ float g_bufA[ROWS*DD];
__device__ float g_bufB[ROWS*DD];
__device__ float g_acc[ROWS*DD];
__device__ float g_part[(size_t)2*ROWS*DD];     /* split-K partials, 128MB */
__device__ float g_cum[ROWS];
__device__ float g_scores[ROWS*MM];
__device__ int   g_flag[ROWS];
__device__ float g_colmax[BB*MM];
__device__ float g_colsum[BB*MM];
__device__ float g_mem[BB*MM*DD];
__device__ float g_mA[BB*MM*DD];
/* fp16 GEMM operands */
__device__ __half g_Af[(size_t)ROWS*DD];        /* LN(hidden) fp16 */
__device__ __half g_act[(size_t)ROWS*DI_];      /* gelu activations fp16 */
__device__ __half g_Wu[(size_t)DI_*DD];         /* W_up^T  [4096,1024] fp16 */
__device__ __half g_Wd[(size_t)DD*DI_];         /* W_down^T [1024,4096] fp16 */

/* ==================== PTX helpers ========================================= */
__device__ __forceinline__ uint32_t smem_u32(const void* p){
    uint32_t a;
    asm("{ .reg .u64 t; cvta.to.shared.u64 t, %1; cvt.u32.u64 %0, t; }" : "=r"(a) : "l"(p));
    return a;
}
#define SMEM_SWIZZLE_128B(off) ((off) ^ (((off) >> 3) & 0x70))

__device__ __forceinline__ void cp16(uint32_t dst, const void* src){
    asm volatile("cp.async.cg.shared.global [%0], [%1], 16;" :: "r"(dst), "l"(src));
}
#define CP_COMMIT() asm volatile("cp.async.commit_group;" ::: "memory")
#define CP_WAIT1()  asm volatile("cp.async.wait_group 1;" ::: "memory")

__device__ __forceinline__ void ldsm4(uint32_t addr, uint32_t r[4]){
    asm volatile("ldmatrix.sync.aligned.m8n8.x4.shared.b16 {%0,%1,%2,%3}, [%4];"
        : "=r"(r[0]), "=r"(r[1]), "=r"(r[2]), "=r"(r[3]) : "r"(addr));
}
__device__ __forceinline__ void mma16816(float c[4], uint32_t a0, uint32_t a1,
                                         uint32_t a2, uint32_t a3,
                                         uint32_t b0, uint32_t b1){
    asm volatile("mma.sync.aligned.m16n8k16.row.col.f32.f16.f16.f32 "
        "{%0,%1,%2,%3}, {%4,%5,%6,%7}, {%8,%9}, {%0,%1,%2,%3};"
        : "+f"(c[0]), "+f"(c[1]), "+f"(c[2]), "+f"(c[3])
        : "r"(a0), "r"(a1), "r"(a2), "r"(a3), "r"(b0), "r"(b1));
}

/* ---------------- reduction helpers -------------------------------------- */
__device__ __forceinline__ float warpRedSum(float v){
#pragma unroll
    for(int o=16;o>0;o>>=1) v += __shfl_xor_sync(0xffffffffu, v, o);
    return v;
}
__device__ __forceinline__ float warpRedMax(float v){
#pragma unroll
    for(int o=16;o>0;o>>=1) v = fmaxf(v, __shfl_xor_sync(0xffffffffu, v, o));
    return v;
}
__device__ float blockRedSum(float v, float* sh){
    int lane = threadIdx.x & 31, w = threadIdx.x >> 5;
    v = warpRedSum(v);
    __syncthreads();
    if(lane==0) sh[w] = v;
    __syncthreads();
    if(threadIdx.x==0){
        float r = sh[0];
#pragma unroll
        for(int i=1;i<8;i++) r += sh[i];
        sh[0] = r;
    }
    __syncthreads();
    return sh[0];
}
__device__ float blockRedMax(float v, float* sh){
    int lane = threadIdx.x & 31, w = threadIdx.x >> 5;
    v = warpRedMax(v);
    __syncthreads();
    if(lane==0) sh[w] = v;
    __syncthreads();
    if(threadIdx.x==0){
        float r = sh[0];
#pragma unroll
        for(int i=1;i<8;i++) r = fmaxf(r, sh[i]);
        sh[0] = r;
    }
    __syncthreads();
    return sh[0];
}

/* ------ weight transpose to fp16: T[n][k] = W[k][n] ----------------------- */
__global__ void __launch_bounds__(256) wtrans_kernel(const float* __restrict__ W,
    int K, int N, __half* __restrict__ T)
{
    __shared__ float t[32][33];
    int x = blockIdx.x*32, y = blockIdx.y*32;
    int tx = threadIdx.x & 31, ty = threadIdx.x >> 5;
#pragma unroll
    for(int j=0;j<32;j+=8) t[ty+j][tx] = W[(size_t)(y+ty+j)*N + x + tx];
    __syncthreads();
#pragma unroll
    for(int j=0;j<32;j+=8){
        float v = t[tx][ty+j];
        int n = x + ty + j, k = y + tx;
        T[(size_t)n*K + k] = __float2half_rn(v);
    }
}

/* ------ per-row LN stats + entropy flag + emit LN'd fp16 A (step 0) ------- */
__global__ void __launch_bounds__(256) rowstat_kernel(const float* __restrict__ X,
    const float* __restrict__ g1, const float* __restrict__ b1,
    __half* __restrict__ Af)
{
    __shared__ float sh[8];
    int row = blockIdx.x;
    const float4 x4 = *((const float4*)(X + (size_t)row*DD) + threadIdx.x);
    float s = x4.x + x4.y + x4.z + x4.w;
    float mean = blockRedSum(s, sh) * (1.0f/DD);
    float sq = x4.x*x4.x + x4.y*x4.y + x4.z*x4.z + x4.w*x4.w;
    float var = blockRedSum(sq, sh) * (1.0f/DD) - mean*mean;
    float rstd = rsqrtf(fmaxf(var, 0.0f) + EPSLN);
    float mx = fmaxf(fmaxf(x4.x,x4.y), fmaxf(x4.z,x4.w));
    mx = blockRedMax(mx, sh);
    float e0=expf(x4.x-mx), e1=expf(x4.y-mx), e2=expf(x4.z-mx), e3=expf(x4.w-mx);
    float se  = e0+e1+e2+e3;
    float sxe = e0*x4.x + e1*x4.y + e2*x4.z + e3*x4.w;
    se  = blockRedSum(se, sh);
    sxe = blockRedSum(sxe, sh);
    if(threadIdx.x==0){
        float logZ = mx + logf(se);
        float ent = (logZ - sxe/se) * (1.0f/logf((float)DD));
        g_flag[row] = (ent > THRG) ? 1 : 0;
    }
    int k0 = threadIdx.x*4;
    float4 gv = *(const float4*)(g1 + k0);
    float4 bv = *(const float4*)(b1 + k0);
    float a0 = (x4.x-mean)*rstd*gv.x + bv.x;
    float a1 = (x4.y-mean)*rstd*gv.y + bv.y;
    float a2 = (x4.z-mean)*rstd*gv.z + bv.z;
    float a3 = (x4.w-mean)*rstd*gv.w + bv.w;
    size_t off = (size_t)row*DD + k0;
    *(__half2*)(Af+off)   = __half2(__float2half_rn(a0), __float2half_rn(a1));
    *(__half2*)(Af+off+2) = __half2(__float2half_rn(a2), __float2half_rn(a3));
}

/* ==================== mma.sync fp16 GEMM ==================================
   CTA tile 128x128, 256 threads, warp tile 64x32, k-chunk 64, 3-stage.
   KDIM = K-range per CTA; KSTRIDE = full row stride; blockIdx.z = K-split.
   EPI==0: up (bias + exact GELU -> fp16, Ntot=4096)
   EPI==2: down partial (raw fp32 -> Pout + z*ROWS*DD, Ntot=1024)           */
#define STAGE_BYTES 32768          /* A 16KB + B 16KB */
#define NSTAGE 3
#define SMEMSZ (NSTAGE*STAGE_BYTES)

template<int KDIM, int KSTRIDE, int EPI>
__global__ void __launch_bounds__(256,2) gemm_mma(
    const __half* __restrict__ A, const __half* __restrict__ B,
    const float* __restrict__ bias,
    float* __restrict__ Pout,
    __half* __restrict__ Oh)
{
    extern __shared__ char smem[];
    uint32_t sb = smem_u32(smem);
    const int tid  = threadIdx.x;
    const int lane = tid & 31;
    const int warp = tid >> 5;
    const int wm = warp >> 2;
    const int wn = warp & 3;
    const int mBase = blockIdx.y*128, nBase = blockIdx.x*128;
    const int kBase = blockIdx.z*KDIM;
    constexpr int NKC = KDIM/64;
    constexpr int NTOT = (EPI==0) ? DI_ : DD;

    float acc[4][4][4];
#pragma unroll
    for(int i=0;i<4;i++)
#pragma unroll
        for(int j=0;j<4;j++)
#pragma unroll
            for(int q=0;q<4;q++) acc[i][j][q]=0.0f;

    const int cprow = tid>>3, cpg = tid&7;

    auto load_chunk = [&](int ck, int st){
        int kk = kBase + ck*64;
        uint32_t ab = sb + st*STAGE_BYTES;
        uint32_t bb = ab + 16384;
        uint32_t so = SMEM_SWIZZLE_128B((uint32_t)(cprow*128 + cpg*16));
#pragma unroll
        for(int r=0;r<128;r+=32){
            cp16(ab + so + r*128, A + (size_t)(mBase+cprow+r)*KSTRIDE + kk + cpg*8);
            cp16(bb + so + r*128, B + (size_t)(nBase+cprow+r)*KSTRIDE + kk + cpg*8);
        }
    };

    const int a_lrow = lane & 15;
    const int a_lk   = (lane >> 4) * 8;
    const int b_nrow = (lane & 7) + ((lane >> 4) * 8);
    const int b_bk   = ((lane >> 3) & 1) * 8;

    load_chunk(0, 0); CP_COMMIT();
    load_chunk(1, 1); CP_COMMIT();

    for(int ck=0; ck<NKC; ck++){
        int st = ck % NSTAGE;
        CP_WAIT1();
        __syncthreads();
        int pf = ck + 2;
        if(pf < NKC) load_chunk(pf, pf % NSTAGE);
        CP_COMMIT();

        uint32_t aB = sb + st*STAGE_BYTES;
        uint32_t bB = aB + 16384;
#pragma unroll
        for(int k16=0;k16<4;k16++){
            uint32_t a[4][4];
#pragma unroll
            for(int i=0;i<4;i++){
                uint32_t off = (uint32_t)((wm*64 + i*16 + a_lrow)*128 + (k16*16 + a_lk)*2);
                ldsm4(aB + SMEM_SWIZZLE_128B(off), a[i]);
            }
            uint32_t b[2][4];
#pragma unroll
            for(int j2=0;j2<2;j2++){
                uint32_t off = (uint32_t)((wn*32 + j2*16 + b_nrow)*128 + (k16*16 + b_bk)*2);
                ldsm4(bB + SMEM_SWIZZLE_128B(off), b[j2]);
            }
#pragma unroll
            for(int i=0;i<4;i++)
#pragma unroll
                for(int j=0;j<4;j++)
                    mma16816(acc[i][j], a[i][0], a[i][1], a[i][2], a[i][3],
                             b[j>>1][(j&1)*2], b[j>>1][(j&1)*2+1]);
        }
    }

    /* epilogue */
    const float S2 = 0.70710678118654752440f;
    float* P = (EPI==2) ? (Pout + (size_t)blockIdx.z*ROWS*DD) : Pout;
#pragma unroll
    for(int i=0;i<4;i++){
        int row0 = mBase + wm*64 + i*16 + (lane>>2);
#pragma unroll
        for(int j=0;j<4;j++){
            int col = nBase + wn*32 + j*8 + (lane&3)*2;
#pragma unroll
            for(int h=0;h<2;h++){
                int row = row0 + h*8;
                size_t off = (size_t)row*NTOT + col;
                if(EPI==0){
                    float v0 = acc[i][j][h*2]   + bias[col];
                    float v1 = acc[i][j][h*2+1] + bias[col+1];
                    float q0 = 0.5f*v0*(1.0f+erff(v0*S2));
                    float q1 = 0.5f*v1*(1.0f+erff(v1*S2));
                    *(__half2*)(Oh+off) = __half2(__float2half_rn(q0), __float2half_rn(q1));
                } else {
                    float2 o; o.x = acc[i][j][h*2]; o.y = acc[i][j][h*2+1];
                    *(float2*)(P + off) = o;
                }
            }
        }
    }
}

/* ------ reduce split-K partials + bias + residual -> h_new; scores -------- */
__global__ void __launch_bounds__(256) reduce_scores_kernel(
    const float* __restrict__ Hin, float* __restrict__ Hout,
    const float* __restrict__ bias,
    const float* __restrict__ Wc, const float* __restrict__ bc)
{
    __shared__ float sW[DD*9];          /* padded [k][m], 36KB */
    __shared__ float sred[8*9];
    for(int i=threadIdx.x;i<DD*8;i+=256){ int k=i>>3, m=i&7; sW[k*9+m]=Wc[i]; }

    int row = blockIdx.x;
    size_t off = (size_t)row*DD + threadIdx.x*4;
    float4 p0 = *(const float4*)(g_part + off);
    float4 p1 = *(const float4*)(g_part + (size_t)ROWS*DD + off);
    float4 hv = *(const float4*)(Hin + off);
    float4 bv = *(const float4*)(bias + threadIdx.x*4);
    float4 o;
    o.x = p0.x + p1.x + bv.x + hv.x;
    o.y = p0.y + p1.y + bv.y + hv.y;
    o.z = p0.z + p1.z + bv.z + hv.z;
    o.w = p0.w + p1.w + bv.w + hv.w;
    *(float4*)(Hout + off) = o;
    __syncthreads();

    int k0 = threadIdx.x*4;
    float h[4] = {o.x, o.y, o.z, o.w};
    float acc[8] = {0,0,0,0,0,0,0,0};
#pragma unroll
    for(int j=0;j<4;j++){
        float x = h[j];
        const float* wr = &sW[(k0+j)*9];
#pragma unroll
        for(int m=0;m<8;m++) acc[m] += x*wr[m];
    }
    int lane = threadIdx.x & 31, warp = threadIdx.x >> 5;
#pragma unroll
    for(int m=0;m<8;m++){
        acc[m] = warpRedSum(acc[m]);
        if(lane==0) sred[warp*9+m] = acc[m];
    }
    __syncthreads();
    if(threadIdx.x<8){
        float r = 0.0f;
#pragma unroll
        for(int w=0;w<8;w++) r += sred[w*9+threadIdx.x];
        g_scores[(size_t)row*8+threadIdx.x] = r + bc[threadIdx.x];
    }
}

/* ------------- column softmax stats over L, zero memory/mA --------------- */
__global__ void __launch_bounds__(256) colstats_kernel(){
    __shared__ float sh[8];
    int c = blockIdx.x; int b = c>>3, m = c&7;
    const float* sc = g_scores + (size_t)b*LL*8 + m;
    float v[16];
#pragma unroll
    for(int i=0;i<16;i++) v[i] = sc[(size_t)(threadIdx.x + i*256)*8];
    float mx = -1e30f;
#pragma unroll
    for(int i=0;i<16;i++) mx = fmaxf(mx, v[i]);
    mx = blockRedMax(mx, sh);
    float se = 0.0f;
#pragma unroll
    for(int i=0;i<16;i++) se += expf(v[i]-mx);
    se = blockRedSum(se, sh);
    if(threadIdx.x==0){ g_colmax[c]=mx; g_colsum[c]=se; }
    float4 z = {0,0,0,0};
    ((float4*)(g_mem + (size_t)c*DD))[threadIdx.x] = z;
    ((float4*)(g_mA  + (size_t)c*DD))[threadIdx.x] = z;
}

/* ------------- memory[b,m,:] += sum_l P[l,m] * h[l,:] --------------------- */
__global__ void __launch_bounds__(256) memacc_kernel(const float* __restrict__ H){
    __shared__ float sp[128*8];
    int b = blockIdx.y; int lb = blockIdx.x*128;
    if(threadIdx.x<128){
        int l = lb + threadIdx.x;
#pragma unroll
        for(int m=0;m<8;m++){
            int c = b*8+m;
            sp[threadIdx.x*8+m] = expf(g_scores[((size_t)b*LL+l)*8+m]-g_colmax[c]) / g_colsum[c];
        }
    }
    __syncthreads();
    float4 acc[8];
#pragma unroll
    for(int m=0;m<8;m++){ acc[m].x=0;acc[m].y=0;acc[m].z=0;acc[m].w=0; }
    const float4* hb = (const float4*)(H + ((size_t)b*LL+lb)*DD) + threadIdx.x;
    for(int l=0;l<128;l++){
        float4 h = hb[(size_t)l*(DD/4)];
#pragma unroll
        for(int m=0;m<8;m++){
            float p = sp[l*8+m];
            acc[m].x += p*h.x; acc[m].y += p*h.y; acc[m].z += p*h.z; acc[m].w += p*h.w;
        }
    }
    int d0 = threadIdx.x*4;
#pragma unroll
    for(int m=0;m<8;m++){
        float* mp = g_mem + ((size_t)b*8+m)*DD + d0;
        atomicAdd(mp+0,acc[m].x); atomicAdd(mp+1,acc[m].y);
        atomicAdd(mp+2,acc[m].z); atomicAdd(mp+3,acc[m].w);
    }
}

/* ------------- mA[b,m,:] = memory[b,m,:] @ W_attn ------------------------- */
__global__ void __launch_bounds__(256) memattn_kernel(const float* __restrict__ Wa){
    __shared__ float sM[8][256];
    int b  = blockIdx.x;
    int nb = blockIdx.y*256;
    int ks = blockIdx.z*256;
    for(int i=threadIdx.x;i<8*256;i+=256){
        int m=i>>8, k=i&255;
        sM[m][k] = g_mem[((size_t)b*8+m)*DD + ks + k];
    }
    __syncthreads();
    int n = nb + threadIdx.x;
    float acc[8] = {0,0,0,0,0,0,0,0};
    for(int k=0;k<256;k++){
        float w = Wa[(size_t)(ks+k)*DD + n];
#pragma unroll
        for(int m=0;m<8;m++) acc[m] += sM[m][k]*w;
    }
#pragma unroll
    for(int m=0;m<8;m++) atomicAdd(&g_mA[((size_t)b*8+m)*DD+n], acc[m]);
}

/* ------------- h_new += softmax_m(scores) @ mA + b_attn ------------------- */
__global__ void __launch_bounds__(256) ctxattn_kernel(float* __restrict__ H,
    const float* __restrict__ ba)
{
    __shared__ float sMA[8*DD];
    __shared__ float sp[32*8];
    int b = blockIdx.y; int rb = blockIdx.x*32;
    for(int i=threadIdx.x;i<8*DD;i+=256) sMA[i] = g_mA[(size_t)b*8*DD + i];
    if(threadIdx.x<32){
        int l = rb + threadIdx.x;
        float s[8]; float mx = -1e30f;
#pragma unroll
        for(int m=0;m<8;m++){ s[m]=g_scores[((size_t)b*LL+l)*8+m]; mx=fmaxf(mx,s[m]); }
        float se=0.0f;
#pragma unroll
        for(int m=0;m<8;m++){ s[m]=expf(s[m]-mx); se+=s[m]; }
        float inv = 1.0f/se;
#pragma unroll
        for(int m=0;m<8;m++) sp[threadIdx.x*8+m] = s[m]*inv;
    }
    __syncthreads();
    int d0 = threadIdx.x*4;
    float4 bv = *(const float4*)(ba + d0);
    for(int r=0;r<32;r++){
        size_t off = ((size_t)b*LL + rb + r)*DD + d0;
        float4 h = *(float4*)(H + off);
#pragma unroll
        for(int m=0;m<8;m++){
            float p = sp[r*8+m];
            float4 mv = *(const float4*)(&sMA[m*DD + d0]);
            h.x += p*mv.x; h.y += p*mv.y; h.z += p*mv.z; h.w += p*mv.w;
        }
        h.x += bv.x; h.y += bv.y; h.z += bv.z; h.w += bv.w;
        *(float4*)(H + off) = h;
    }
}

/* ------ gate (entropy) + halting + ACT + next-step LN stats + Af ---------- */
__global__ void __launch_bounds__(256) gatestat_kernel(float* __restrict__ Hn,
    const float* __restrict__ Hold,
    const float* __restrict__ Wh, const float* __restrict__ bh,
    const float* __restrict__ g1, const float* __restrict__ b1,
    __half* __restrict__ Af, int emit)
{
    __shared__ float sh[8];
    int row = blockIdx.x;
    int upd = g_flag[row];
    size_t off = (size_t)row*DD + threadIdx.x*4;
    float4 v;
    if(upd){
        v = *(const float4*)(Hn + off);
    } else {
        v = *(const float4*)(Hold + off);
        *(float4*)(Hn + off) = v;
    }
    float4 w4 = *(const float4*)(Wh + threadIdx.x*4);
    float d = v.x*w4.x + v.y*w4.y + v.z*w4.z + v.w*w4.w;
    d = blockRedSum(d, sh);
    float p = 1.0f/(1.0f + expf(-(d + bh[0])));
    float cum = g_cum[row];
    float w = p*(1.0f - cum);
    float4 a = *(float4*)(g_acc + off);
    a.x += w*v.x; a.y += w*v.y; a.z += w*v.z; a.w += w*v.w;
    *(float4*)(g_acc + off) = a;
    if(threadIdx.x==0) g_cum[row] = cum + w;

    if(!emit) return;
    float s = v.x + v.y + v.z + v.w;
    float mean = blockRedSum(s, sh) * (1.0f/DD);
    float sq = v.x*v.x + v.y*v.y + v.z*v.z + v.w*v.w;
    float var = blockRedSum(sq, sh) * (1.0f/DD) - mean*mean;
    float rstd = rsqrtf(fmaxf(var, 0.0f) + EPSLN);
    float mx = fmaxf(fmaxf(v.x,v.y), fmaxf(v.z,v.w));
    mx = blockRedMax(mx, sh);
    float e0=expf(v.x-mx), e1=expf(v.y-mx), e2=expf(v.z-mx), e3=expf(v.w-mx);
    float se  = e0+e1+e2+e3;
    float sxe = e0*v.x + e1*v.y + e2*v.z + e3*v.w;
    se  = blockRedSum(se, sh);
    sxe = blockRedSum(sxe, sh);
    if(threadIdx.x==0){
        float logZ = mx + logf(se);
        float ent = (logZ - sxe/se) * (1.0f/logf((float)DD));
        g_flag[row] = (ent > THRG) ? 1 : 0;
    }
    int k0 = threadIdx.x*4;
    float4 gv = *(const float4*)(g1 + k0);
    float4 bv = *(const float4*)(b1 + k0);
    float a0 = (v.x-mean)*rstd*gv.x + bv.x;
    float a1 = (v.y-mean)*rstd*gv.y + bv.y;
    float a2 = (v.z-mean)*rstd*gv.z + bv.z;
    float a3 = (v.w-mean)*rstd*gv.w + bv.w;
    size_t o2 = (size_t)row*DD + k0;
    *(__half2*)(Af+o2)   = __half2(__float2half_rn(a0), __float2half_rn(a1));
    *(__half2*)(Af+o2+2) = __half2(__float2half_rn(a2), __float2half_rn(a3));
}

/* ------------- out = LN(acc + (1-cum)*hidden; g2,b2) ---------------------- */
__global__ void __launch_bounds__(256) final_kernel(const float* __restrict__ Hid,
    const float* __restrict__ g2, const float* __restrict__ b2,
    float* __restrict__ out)
{
    __shared__ float sh[8];
    int row = blockIdx.x;
    size_t off = (size_t)row*DD + threadIdx.x*4;
    float r = 1.0f - g_cum[row];
    float4 a = *(const float4*)(g_acc + off);
    float4 h = *(const float4*)(Hid + off);
    float4 o;
    o.x = a.x + r*h.x; o.y = a.y + r*h.y; o.z = a.z + r*h.z; o.w = a.w + r*h.w;
    float s = o.x+o.y+o.z+o.w;
    float mean = blockRedSum(s, sh) * (1.0f/DD);
    float sq = o.x*o.x + o.y*o.y + o.z*o.z + o.w*o.w;
    float var = blockRedSum(sq, sh) * (1.0f/DD) - mean*mean;
    float rstd = rsqrtf(fmaxf(var,0.0f) + EPSLN);
    float4 gv = *(const float4*)(g2 + threadIdx.x*4);
    float4 bv = *(const float4*)(b2 + threadIdx.x*4);
    float4 y;
    y.x = (o.x-mean)*rstd*gv.x + bv.x;
    y.y = (o.y-mean)*rstd*gv.y + bv.y;
    y.z = (o.z-mean)*rstd*gv.z + bv.z;
    y.w = (o.w-mean)*rstd*gv.w + bv.w;
    *(float4*)(out + off) = y;
}

/* ---------------- host launcher ------------------------------------------- */
extern "C" void kernel_launch(void* const* d_in, const int* in_sizes, int n_in,
                              void* d_out, int out_size)
{
    const float* x      = (const float*)d_in[0];
    const float* g1     = (const float*)d_in[1];
    const float* b1     = (const float*)d_in[2];
    const float* W_up   = (const float*)d_in[3];
    const float* b_up   = (const float*)d_in[4];
    const float* W_down = (const float*)d_in[5];
    const float* b_down = (const float*)d_in[6];
    const float* W_halt = (const float*)d_in[7];
    const float* b_halt = (const float*)d_in[8];
    const float* W_comp = (const float*)d_in[9];
    const float* b_comp = (const float*)d_in[10];
    const float* W_attn = (const float*)d_in[11];
    const float* b_attn = (const float*)d_in[12];
    const float* g2     = (const float*)d_in[13];
    const float* b2     = (const float*)d_in[14];
    float* out = (float*)d_out;

    static int attr_set = 0;
    if(!attr_set){
        cudaFuncSetAttribute((const void*)gemm_mma<1024,1024,0>,
                             cudaFuncAttributeMaxDynamicSharedMemorySize, SMEMSZ);
        cudaFuncSetAttribute((const void*)gemm_mma<2048,4096,2>,
                             cudaFuncAttributeMaxDynamicSharedMemorySize, SMEMSZ);
        attr_set = 1;
    }

    float *bufA, *bufB, *acc, *cum, *part;
    __half *Af, *act, *Wu, *Wd;
    cudaGetSymbolAddress((void**)&bufA, g_bufA);
    cudaGetSymbolAddress((void**)&bufB, g_bufB);
    cudaGetSymbolAddress((void**)&acc,  g_acc);
    cudaGetSymbolAddress((void**)&cum,  g_cum);
    cudaGetSymbolAddress((void**)&part, g_part);
    cudaGetSymbolAddress((void**)&Af,   g_Af);
    cudaGetSymbolAddress((void**)&act,  g_act);
    cudaGetSymbolAddress((void**)&Wu,   g_Wu);
    cudaGetSymbolAddress((void**)&Wd,   g_Wd);

    cudaMemcpyAsync(bufA, x, sizeof(float)*(size_t)ROWS*DD, cudaMemcpyDeviceToDevice, 0);
    cudaMemsetAsync(acc, 0, sizeof(float)*(size_t)ROWS*DD, 0);
    cudaMemsetAsync(cum, 0, sizeof(float)*ROWS, 0);

    wtrans_kernel<<<dim3(DI_/32, DD/32),256>>>(W_up,   DD,  DI_, Wu);
    wtrans_kernel<<<dim3(DD/32, DI_/32),256>>>(W_down, DI_, DD,  Wd);

    rowstat_kernel<<<ROWS,256>>>(bufA, g1, b1, Af);

    float* hid = bufA;
    float* hnw = bufB;
    for(int s=0;s<4;s++){
        gemm_mma<1024,1024,0><<<dim3(DI_/128, ROWS/128),256,SMEMSZ>>>(
            Af, Wu, b_up, nullptr, act);
        gemm_mma<2048,4096,2><<<dim3(DD/128, ROWS/128, 2),256,SMEMSZ>>>(
            act, Wd, nullptr, part, nullptr);
        reduce_scores_kernel<<<ROWS,256>>>(hid, hnw, b_down, W_comp, b_comp);
        colstats_kernel<<<BB*MM,256>>>();
        memacc_kernel<<<dim3(LL/128,BB),256>>>(hnw);
        memattn_kernel<<<dim3(BB,4,4),256>>>(W_attn);
        ctxattn_kernel<<<dim3(LL/32,BB),256>>>(hnw, b_attn);
        gatestat_kernel<<<ROWS,256>>>(hnw, hid, W_halt, b_halt, g1, b1, Af, (s<3)?1:0);
        float* t = hid; hid = hnw; hnw = t;
    }
    final_kernel<<<ROWS,256>>>(hid, g2, b2, out);
}

// round 10
// speedup vs baseline: 1.1064x; 1.1064x over previous
#include <cuda_runtime.h>
#include <cuda_fp16.h>
#include <math.h>
#include <stdint.h>

#define BB 4
#define LL 4096
#define DD 1024
#define DI_ 4096
#define MM 8
#define ROWS (BB*LL)          /* 16384 */
#define THRG 0.5f
#define EPSLN 1e-6f

/* ---------------- scratch (device globals; no allocations allowed) -------- */
__device__ float g_bufA[ROWS*DD];
__device__ float g_bufB[ROWS*DD];
__device__ float g_acc[ROWS*DD];
__device__ float g_cum[ROWS];
__device__ float g_scores[ROWS*MM];
__device__ int   g_flag[ROWS];
__device__ float g_colmax[BB*MM];
__device__ float g_colsum[BB*MM];
__device__ float g_mem[BB*MM*DD];
__device__ float g_mA[BB*MM*DD];
/* fp16 GEMM operands */
__device__ __half g_Af[(size_t)ROWS*DD];        /* LN(hidden) fp16 */
__device__ __half g_act[(size_t)ROWS*DI_];      /* gelu activations fp16 */
__device__ __half g_Wu[(size_t)DI_*DD];         /* W_up^T  [4096,1024] fp16 */
__device__ __half g_Wd[(size_t)DD*DI_];         /* W_down^T [1024,4096] fp16 */

/* ==================== PTX helpers ========================================= */
__device__ __forceinline__ uint32_t smem_u32(const void* p){
    uint32_t a;
    asm("{ .reg .u64 t; cvta.to.shared.u64 t, %1; cvt.u32.u64 %0, t; }" : "=r"(a) : "l"(p));
    return a;
}
#define SMEM_SWIZZLE_128B(off) ((off) ^ (((off) >> 3) & 0x70))

__device__ __forceinline__ void cp16(uint32_t dst, const void* src){
    asm volatile("cp.async.cg.shared.global [%0], [%1], 16;" :: "r"(dst), "l"(src));
}
#define CP_COMMIT() asm volatile("cp.async.commit_group;" ::: "memory")
#define CP_WAIT1()  asm volatile("cp.async.wait_group 1;" ::: "memory")

__device__ __forceinline__ void ldsm4(uint32_t addr, uint32_t r[4]){
    asm volatile("ldmatrix.sync.aligned.m8n8.x4.shared.b16 {%0,%1,%2,%3}, [%4];"
        : "=r"(r[0]), "=r"(r[1]), "=r"(r[2]), "=r"(r[3]) : "r"(addr));
}
__device__ __forceinline__ void mma16816(float c[4], uint32_t a0, uint32_t a1,
                                         uint32_t a2, uint32_t a3,
                                         uint32_t b0, uint32_t b1){
    asm volatile("mma.sync.aligned.m16n8k16.row.col.f32.f16.f16.f32 "
        "{%0,%1,%2,%3}, {%4,%5,%6,%7}, {%8,%9}, {%0,%1,%2,%3};"
        : "+f"(c[0]), "+f"(c[1]), "+f"(c[2]), "+f"(c[3])
        : "r"(a0), "r"(a1), "r"(a2), "r"(a3), "r"(b0), "r"(b1));
}

/* ---------------- reduction helpers -------------------------------------- */
__device__ __forceinline__ float warpRedSum(float v){
#pragma unroll
    for(int o=16;o>0;o>>=1) v += __shfl_xor_sync(0xffffffffu, v, o);
    return v;
}
__device__ __forceinline__ float warpRedMax(float v){
#pragma unroll
    for(int o=16;o>0;o>>=1) v = fmaxf(v, __shfl_xor_sync(0xffffffffu, v, o));
    return v;
}
__device__ float blockRedSum(float v, float* sh){
    int lane = threadIdx.x & 31, w = threadIdx.x >> 5;
    v = warpRedSum(v);
    __syncthreads();
    if(lane==0) sh[w] = v;
    __syncthreads();
    if(threadIdx.x==0){
        float r = sh[0];
#pragma unroll
        for(int i=1;i<8;i++) r += sh[i];
        sh[0] = r;
    }
    __syncthreads();
    return sh[0];
}
__device__ float blockRedMax(float v, float* sh){
    int lane = threadIdx.x & 31, w = threadIdx.x >> 5;
    v = warpRedMax(v);
    __syncthreads();
    if(lane==0) sh[w] = v;
    __syncthreads();
    if(threadIdx.x==0){
        float r = sh[0];
#pragma unroll
        for(int i=1;i<8;i++) r = fmaxf(r, sh[i]);
        sh[0] = r;
    }
    __syncthreads();
    return sh[0];
}

/* ------ weight transpose to fp16: T[n][k] = W[k][n] ----------------------- */
__global__ void __launch_bounds__(256) wtrans_kernel(const float* __restrict__ W,
    int K, int N, __half* __restrict__ T)
{
    __shared__ float t[32][33];
    int x = blockIdx.x*32, y = blockIdx.y*32;
    int tx = threadIdx.x & 31, ty = threadIdx.x >> 5;
#pragma unroll
    for(int j=0;j<32;j+=8) t[ty+j][tx] = W[(size_t)(y+ty+j)*N + x + tx];
    __syncthreads();
#pragma unroll
    for(int j=0;j<32;j+=8){
        float v = t[tx][ty+j];
        int n = x + ty + j, k = y + tx;
        T[(size_t)n*K + k] = __float2half_rn(v);
    }
}

/* ------ per-row LN stats + entropy flag + emit LN'd fp16 A (step 0) ------- */
__global__ void __launch_bounds__(256) rowstat_kernel(const float* __restrict__ X,
    const float* __restrict__ g1, const float* __restrict__ b1,
    __half* __restrict__ Af)
{
    __shared__ float sh[8];
    int row = blockIdx.x;
    const float4 x4 = *((const float4*)(X + (size_t)row*DD) + threadIdx.x);
    float s = x4.x + x4.y + x4.z + x4.w;
    float mean = blockRedSum(s, sh) * (1.0f/DD);
    float sq = x4.x*x4.x + x4.y*x4.y + x4.z*x4.z + x4.w*x4.w;
    float var = blockRedSum(sq, sh) * (1.0f/DD) - mean*mean;
    float rstd = rsqrtf(fmaxf(var, 0.0f) + EPSLN);
    float mx = fmaxf(fmaxf(x4.x,x4.y), fmaxf(x4.z,x4.w));
    mx = blockRedMax(mx, sh);
    float e0=expf(x4.x-mx), e1=expf(x4.y-mx), e2=expf(x4.z-mx), e3=expf(x4.w-mx);
    float se  = e0+e1+e2+e3;
    float sxe = e0*x4.x + e1*x4.y + e2*x4.z + e3*x4.w;
    se  = blockRedSum(se, sh);
    sxe = blockRedSum(sxe, sh);
    if(threadIdx.x==0){
        float logZ = mx + logf(se);
        float ent = (logZ - sxe/se) * (1.0f/logf((float)DD));
        g_flag[row] = (ent > THRG) ? 1 : 0;
    }
    int k0 = threadIdx.x*4;
    float4 gv = *(const float4*)(g1 + k0);
    float4 bv = *(const float4*)(b1 + k0);
    float a0 = (x4.x-mean)*rstd*gv.x + bv.x;
    float a1 = (x4.y-mean)*rstd*gv.y + bv.y;
    float a2 = (x4.z-mean)*rstd*gv.z + bv.z;
    float a3 = (x4.w-mean)*rstd*gv.w + bv.w;
    size_t off = (size_t)row*DD + k0;
    *(__half2*)(Af+off)   = __half2(__float2half_rn(a0), __float2half_rn(a1));
    *(__half2*)(Af+off+2) = __half2(__float2half_rn(a2), __float2half_rn(a3));
}

/* ==================== mma.sync fp16 GEMM ==================================
   C[M, Ntot] = A[M,K] * B^T,  fp16 operands, fp32 accumulate.
   CTA tile 128x128, 256 threads, warp tile 64x32, k-chunk 64, 3-stage.
   EPI==0: up (bias + exact GELU -> fp16, Ntot=4096)
   EPI==1: down (bias + residual -> fp32, Ntot=1024)                        */
#define STAGE_BYTES 32768          /* A 16KB + B 16KB */
#define NSTAGE 3
#define SMEMSZ (NSTAGE*STAGE_BYTES)

template<int KDIM, int EPI>
__global__ void __launch_bounds__(256,2) gemm_mma(
    const __half* __restrict__ A, const __half* __restrict__ B,
    const float* __restrict__ bias,
    const float* __restrict__ Hin, float* __restrict__ Hout,
    __half* __restrict__ Oh)
{
    extern __shared__ char smem[];
    uint32_t sb = smem_u32(smem);
    const int tid  = threadIdx.x;
    const int lane = tid & 31;
    const int warp = tid >> 5;
    const int wm = warp >> 2;
    const int wn = warp & 3;
    const int mBase = blockIdx.y*128, nBase = blockIdx.x*128;
    constexpr int NKC = KDIM/64;
    constexpr int NTOT = (EPI==0) ? DI_ : DD;

    float acc[4][4][4];
#pragma unroll
    for(int i=0;i<4;i++)
#pragma unroll
        for(int j=0;j<4;j++)
#pragma unroll
            for(int q=0;q<4;q++) acc[i][j][q]=0.0f;

    const int cprow = tid>>3, cpg = tid&7;

    auto load_chunk = [&](int ck, int st){
        int kk = ck*64;
        uint32_t ab = sb + st*STAGE_BYTES;
        uint32_t bb = ab + 16384;
        uint32_t so = SMEM_SWIZZLE_128B((uint32_t)(cprow*128 + cpg*16));
#pragma unroll
        for(int r=0;r<128;r+=32){
            cp16(ab + so + r*128, A + (size_t)(mBase+cprow+r)*KDIM + kk + cpg*8);
            cp16(bb + so + r*128, B + (size_t)(nBase+cprow+r)*KDIM + kk + cpg*8);
        }
    };

    const int a_lrow = lane & 15;
    const int a_lk   = (lane >> 4) * 8;
    const int b_nrow = (lane & 7) + ((lane >> 4) * 8);
    const int b_bk   = ((lane >> 3) & 1) * 8;

    load_chunk(0, 0); CP_COMMIT();
    load_chunk(1, 1); CP_COMMIT();

    for(int ck=0; ck<NKC; ck++){
        int st = ck % NSTAGE;
        CP_WAIT1();
        __syncthreads();
        int pf = ck + 2;
        if(pf < NKC) load_chunk(pf, pf % NSTAGE);
        CP_COMMIT();

        uint32_t aB = sb + st*STAGE_BYTES;
        uint32_t bB = aB + 16384;
#pragma unroll
        for(int k16=0;k16<4;k16++){
            uint32_t a[4][4];
#pragma unroll
            for(int i=0;i<4;i++){
                uint32_t off = (uint32_t)((wm*64 + i*16 + a_lrow)*128 + (k16*16 + a_lk)*2);
                ldsm4(aB + SMEM_SWIZZLE_128B(off), a[i]);
            }
            uint32_t b[2][4];
#pragma unroll
            for(int j2=0;j2<2;j2++){
                uint32_t off = (uint32_t)((wn*32 + j2*16 + b_nrow)*128 + (k16*16 + b_bk)*2);
                ldsm4(bB + SMEM_SWIZZLE_128B(off), b[j2]);
            }
#pragma unroll
            for(int i=0;i<4;i++)
#pragma unroll
                for(int j=0;j<4;j++)
                    mma16816(acc[i][j], a[i][0], a[i][1], a[i][2], a[i][3],
                             b[j>>1][(j&1)*2], b[j>>1][(j&1)*2+1]);
        }
    }

    /* epilogue */
    const float S2 = 0.70710678118654752440f;
#pragma unroll
    for(int i=0;i<4;i++){
        int row0 = mBase + wm*64 + i*16 + (lane>>2);
#pragma unroll
        for(int j=0;j<4;j++){
            int col = nBase + wn*32 + j*8 + (lane&3)*2;
            float bx = bias[col], by = bias[col+1];
#pragma unroll
            for(int h=0;h<2;h++){
                int row = row0 + h*8;
                float v0 = acc[i][j][h*2]   + bx;
                float v1 = acc[i][j][h*2+1] + by;
                size_t off = (size_t)row*NTOT + col;
                if(EPI==0){
                    float q0 = 0.5f*v0*(1.0f+erff(v0*S2));
                    float q1 = 0.5f*v1*(1.0f+erff(v1*S2));
                    *(__half2*)(Oh+off) = __half2(__float2half_rn(q0), __float2half_rn(q1));
                } else {
                    float2 hv = *(const float2*)(Hin + off);
                    float2 o; o.x = v0 + hv.x; o.y = v1 + hv.y;
                    *(float2*)(Hout + off) = o;
                }
            }
        }
    }
}

/* ------------- scores = h_new @ W_comp + b_comp  [ROWS, 8] ---------------- */
__global__ void __launch_bounds__(256) scores_kernel(const float* __restrict__ H,
    const float* __restrict__ Wc, const float* __restrict__ bc)
{
    __shared__ float sW[DD*9];
    for(int i=threadIdx.x;i<DD*8;i+=256){ int k=i>>3, m=i&7; sW[k*9+m]=Wc[i]; }
    __syncthreads();
    int warp = threadIdx.x>>5, lane = threadIdx.x&31;
    int row = blockIdx.x*8 + warp;
    const float* hr = H + (size_t)row*DD;
    float acc[8] = {0,0,0,0,0,0,0,0};
    for(int k=lane;k<DD;k+=32){
        float x = hr[k];
#pragma unroll
        for(int m=0;m<8;m++) acc[m] += x*sW[k*9+m];
    }
#pragma unroll
    for(int m=0;m<8;m++) acc[m] = warpRedSum(acc[m]);
    if(lane==0){
#pragma unroll
        for(int m=0;m<8;m++) g_scores[(size_t)row*8+m] = acc[m] + bc[m];
    }
}

/* ------------- column softmax stats over L, zero memory/mA --------------- */
__global__ void __launch_bounds__(256) colstats_kernel(){
    __shared__ float sh[8];
    int c = blockIdx.x; int b = c>>3, m = c&7;
    const float* sc = g_scores + (size_t)b*LL*8 + m;
    float v[16];
#pragma unroll
    for(int i=0;i<16;i++) v[i] = sc[(size_t)(threadIdx.x + i*256)*8];
    float mx = -1e30f;
#pragma unroll
    for(int i=0;i<16;i++) mx = fmaxf(mx, v[i]);
    mx = blockRedMax(mx, sh);
    float se = 0.0f;
#pragma unroll
    for(int i=0;i<16;i++) se += expf(v[i]-mx);
    se = blockRedSum(se, sh);
    if(threadIdx.x==0){ g_colmax[c]=mx; g_colsum[c]=se; }
    float4 z = {0,0,0,0};
    ((float4*)(g_mem + (size_t)c*DD))[threadIdx.x] = z;
    ((float4*)(g_mA  + (size_t)c*DD))[threadIdx.x] = z;
}

/* ------------- memory[b,m,:] += sum_l P[l,m] * h[l,:] --------------------- */
__global__ void __launch_bounds__(256) memacc_kernel(const float* __restrict__ H){
    __shared__ float sp[128*8];
    int b = blockIdx.y; int lb = blockIdx.x*128;
    if(threadIdx.x<128){
        int l = lb + threadIdx.x;
#pragma unroll
        for(int m=0;m<8;m++){
            int c = b*8+m;
            sp[threadIdx.x*8+m] = expf(g_scores[((size_t)b*LL+l)*8+m]-g_colmax[c]) / g_colsum[c];
        }
    }
    __syncthreads();
    float4 acc[8];
#pragma unroll
    for(int m=0;m<8;m++){ acc[m].x=0;acc[m].y=0;acc[m].z=0;acc[m].w=0; }
    const float4* hb = (const float4*)(H + ((size_t)b*LL+lb)*DD) + threadIdx.x;
    for(int l=0;l<128;l++){
        float4 h = hb[(size_t)l*(DD/4)];
#pragma unroll
        for(int m=0;m<8;m++){
            float p = sp[l*8+m];
            acc[m].x += p*h.x; acc[m].y += p*h.y; acc[m].z += p*h.z; acc[m].w += p*h.w;
        }
    }
    int d0 = threadIdx.x*4;
#pragma unroll
    for(int m=0;m<8;m++){
        float* mp = g_mem + ((size_t)b*8+m)*DD + d0;
        atomicAdd(mp+0,acc[m].x); atomicAdd(mp+1,acc[m].y);
        atomicAdd(mp+2,acc[m].z); atomicAdd(mp+3,acc[m].w);
    }
}

/* ------------- mA[b,m,:] = memory[b,m,:] @ W_attn ------------------------- */
__global__ void __launch_bounds__(256) memattn_kernel(const float* __restrict__ Wa){
    __shared__ float sM[8][256];
    int b  = blockIdx.x;
    int nb = blockIdx.y*256;
    int ks = blockIdx.z*256;
    for(int i=threadIdx.x;i<8*256;i+=256){
        int m=i>>8, k=i&255;
        sM[m][k] = g_mem[((size_t)b*8+m)*DD + ks + k];
    }
    __syncthreads();
    int n = nb + threadIdx.x;
    float acc[8] = {0,0,0,0,0,0,0,0};
    for(int k=0;k<256;k++){
        float w = Wa[(size_t)(ks+k)*DD + n];
#pragma unroll
        for(int m=0;m<8;m++) acc[m] += sM[m][k]*w;
    }
#pragma unroll
    for(int m=0;m<8;m++) atomicAdd(&g_mA[((size_t)b*8+m)*DD+n], acc[m]);
}

/* ------------- h_new += softmax_m(scores) @ mA + b_attn ------------------- */
__global__ void __launch_bounds__(256) ctxattn_kernel(float* __restrict__ H,
    const float* __restrict__ ba)
{
    __shared__ float sMA[8*DD];
    __shared__ float sp[32*8];
    int b = blockIdx.y; int rb = blockIdx.x*32;
    for(int i=threadIdx.x;i<8*DD;i+=256) sMA[i] = g_mA[(size_t)b*8*DD + i];
    if(threadIdx.x<32){
        int l = rb + threadIdx.x;
        float s[8]; float mx = -1e30f;
#pragma unroll
        for(int m=0;m<8;m++){ s[m]=g_scores[((size_t)b*LL+l)*8+m]; mx=fmaxf(mx,s[m]); }
        float se=0.0f;
#pragma unroll
        for(int m=0;m<8;m++){ s[m]=expf(s[m]-mx); se+=s[m]; }
        float inv = 1.0f/se;
#pragma unroll
        for(int m=0;m<8;m++) sp[threadIdx.x*8+m] = s[m]*inv;
    }
    __syncthreads();
    int d0 = threadIdx.x*4;
    float4 bv = *(const float4*)(ba + d0);
    for(int r=0;r<32;r++){
        size_t off = ((size_t)b*LL + rb + r)*DD + d0;
        float4 h = *(float4*)(H + off);
#pragma unroll
        for(int m=0;m<8;m++){
            float p = sp[r*8+m];
            float4 mv = *(const float4*)(&sMA[m*DD + d0]);
            h.x += p*mv.x; h.y += p*mv.y; h.z += p*mv.z; h.w += p*mv.w;
        }
        h.x += bv.x; h.y += bv.y; h.z += bv.z; h.w += bv.w;
        *(float4*)(H + off) = h;
    }
}

/* ------ gate (entropy) + halting + ACT + next-step LN stats + Af ---------- */
__global__ void __launch_bounds__(256) gatestat_kernel(float* __restrict__ Hn,
    const float* __restrict__ Hold,
    const float* __restrict__ Wh, const float* __restrict__ bh,
    const float* __restrict__ g1, const float* __restrict__ b1,
    __half* __restrict__ Af, int emit, int first)
{
    __shared__ float sh[8];
    int row = blockIdx.x;
    int upd = g_flag[row];
    size_t off = (size_t)row*DD + threadIdx.x*4;
    float4 v;
    if(upd){
        v = *(const float4*)(Hn + off);
    } else {
        v = *(const float4*)(Hold + off);
        *(float4*)(Hn + off) = v;
    }
    float4 w4 = *(const float4*)(Wh + threadIdx.x*4);
    float d = v.x*w4.x + v.y*w4.y + v.z*w4.z + v.w*w4.w;
    d = blockRedSum(d, sh);
    float p = 1.0f/(1.0f + expf(-(d + bh[0])));
    float cum = first ? 0.0f : g_cum[row];
    float w = p*(1.0f - cum);
    float4 a;
    if(first){
        a.x = w*v.x; a.y = w*v.y; a.z = w*v.z; a.w = w*v.w;
    } else {
        a = *(float4*)(g_acc + off);
        a.x += w*v.x; a.y += w*v.y; a.z += w*v.z; a.w += w*v.w;
    }
    *(float4*)(g_acc + off) = a;
    if(threadIdx.x==0) g_cum[row] = cum + w;

    if(!emit) return;
    /* next-step LN stats + entropy on v (the new hidden) */
    float s = v.x + v.y + v.z + v.w;
    float mean = blockRedSum(s, sh) * (1.0f/DD);
    float sq = v.x*v.x + v.y*v.y + v.z*v.z + v.w*v.w;
    float var = blockRedSum(sq, sh) * (1.0f/DD) - mean*mean;
    float rstd = rsqrtf(fmaxf(var, 0.0f) + EPSLN);
    float mx = fmaxf(fmaxf(v.x,v.y), fmaxf(v.z,v.w));
    mx = blockRedMax(mx, sh);
    float e0=expf(v.x-mx), e1=expf(v.y-mx), e2=expf(v.z-mx), e3=expf(v.w-mx);
    float se  = e0+e1+e2+e3;
    float sxe = e0*v.x + e1*v.y + e2*v.z + e3*v.w;
    se  = blockRedSum(se, sh);
    sxe = blockRedSum(sxe, sh);
    if(threadIdx.x==0){
        float logZ = mx + logf(se);
        float ent = (logZ - sxe/se) * (1.0f/logf((float)DD));
        g_flag[row] = (ent > THRG) ? 1 : 0;
    }
    int k0 = threadIdx.x*4;
    float4 gv = *(const float4*)(g1 + k0);
    float4 bv = *(const float4*)(b1 + k0);
    float a0 = (v.x-mean)*rstd*gv.x + bv.x;
    float a1 = (v.y-mean)*rstd*gv.y + bv.y;
    float a2 = (v.z-mean)*rstd*gv.z + bv.z;
    float a3 = (v.w-mean)*rstd*gv.w + bv.w;
    size_t o2 = (size_t)row*DD + k0;
    *(__half2*)(Af+o2)   = __half2(__float2half_rn(a0), __float2half_rn(a1));
    *(__half2*)(Af+o2+2) = __half2(__float2half_rn(a2), __float2half_rn(a3));
}

/* ------------- out = LN(acc + (1-cum)*hidden; g2,b2) ---------------------- */
__global__ void __launch_bounds__(256) final_kernel(const float* __restrict__ Hid,
    const float* __restrict__ g2, const float* __restrict__ b2,
    float* __restrict__ out)
{
    __shared__ float sh[8];
    int row = blockIdx.x;
    size_t off = (size_t)row*DD + threadIdx.x*4;
    float r = 1.0f - g_cum[row];
    float4 a = *(const float4*)(g_acc + off);
    float4 h = *(const float4*)(Hid + off);
    float4 o;
    o.x = a.x + r*h.x; o.y = a.y + r*h.y; o.z = a.z + r*h.z; o.w = a.w + r*h.w;
    float s = o.x+o.y+o.z+o.w;
    float mean = blockRedSum(s, sh) * (1.0f/DD);
    float sq = o.x*o.x + o.y*o.y + o.z*o.z + o.w*o.w;
    float var = blockRedSum(sq, sh) * (1.0f/DD) - mean*mean;
    float rstd = rsqrtf(fmaxf(var,0.0f) + EPSLN);
    float4 gv = *(const float4*)(g2 + threadIdx.x*4);
    float4 bv = *(const float4*)(b2 + threadIdx.x*4);
    float4 y;
    y.x = (o.x-mean)*rstd*gv.x + bv.x;
    y.y = (o.y-mean)*rstd*gv.y + bv.y;
    y.z = (o.z-mean)*rstd*gv.z + bv.z;
    y.w = (o.w-mean)*rstd*gv.w + bv.w;
    *(float4*)(out + off) = y;
}

/* ---------------- host launcher ------------------------------------------- */
extern "C" void kernel_launch(void* const* d_in, const int* in_sizes, int n_in,
                              void* d_out, int out_size)
{
    const float* x      = (const float*)d_in[0];
    const float* g1     = (const float*)d_in[1];
    const float* b1     = (const float*)d_in[2];
    const float* W_up   = (const float*)d_in[3];
    const float* b_up   = (const float*)d_in[4];
    const float* W_down = (const float*)d_in[5];
    const float* b_down = (const float*)d_in[6];
    const float* W_halt = (const float*)d_in[7];
    const float* b_halt = (const float*)d_in[8];
    const float* W_comp = (const float*)d_in[9];
    const float* b_comp = (const float*)d_in[10];
    const float* W_attn = (const float*)d_in[11];
    const float* b_attn = (const float*)d_in[12];
    const float* g2     = (const float*)d_in[13];
    const float* b2     = (const float*)d_in[14];
    float* out = (float*)d_out;

    static int attr_set = 0;
    if(!attr_set){
        cudaFuncSetAttribute((const void*)gemm_mma<1024,0>,
                             cudaFuncAttributeMaxDynamicSharedMemorySize, SMEMSZ);
        cudaFuncSetAttribute((const void*)gemm_mma<4096,1>,
                             cudaFuncAttributeMaxDynamicSharedMemorySize, SMEMSZ);
        attr_set = 1;
    }

    float *bufA, *bufB;
    __half *Af, *act, *Wu, *Wd;
    cudaGetSymbolAddress((void**)&bufA, g_bufA);
    cudaGetSymbolAddress((void**)&bufB, g_bufB);
    cudaGetSymbolAddress((void**)&Af,   g_Af);
    cudaGetSymbolAddress((void**)&act,  g_act);
    cudaGetSymbolAddress((void**)&Wu,   g_Wu);
    cudaGetSymbolAddress((void**)&Wd,   g_Wd);

    wtrans_kernel<<<dim3(DI_/32, DD/32),256>>>(W_up,   DD,  DI_, Wu);
    wtrans_kernel<<<dim3(DD/32, DI_/32),256>>>(W_down, DI_, DD,  Wd);

    rowstat_kernel<<<ROWS,256>>>(x, g1, b1, Af);

    /* step 0 reads x directly as hidden; ping-pong bufB/bufA afterwards */
    const float* hid = x;
    float* hnw = bufB;
    for(int s=0;s<4;s++){
        gemm_mma<1024,0><<<dim3(DI_/128, ROWS/128),256,SMEMSZ>>>(
            Af, Wu, b_up, nullptr, nullptr, act);
        gemm_mma<4096,1><<<dim3(DD/128, ROWS/128),256,SMEMSZ>>>(
            act, Wd, b_down, hid, hnw, nullptr);
        scores_kernel<<<ROWS/8,256>>>(hnw, W_comp, b_comp);
        colstats_kernel<<<BB*MM,256>>>();
        memacc_kernel<<<dim3(LL/128,BB),256>>>(hnw);
        memattn_kernel<<<dim3(BB,4,4),256>>>(W_attn);
        ctxattn_kernel<<<dim3(LL/32,BB),256>>>(hnw, b_attn);
        gatestat_kernel<<<ROWS,256>>>(hnw, hid, W_halt, b_halt, g1, b1, Af,
                                      (s<3)?1:0, (s==0)?1:0);
        hid = hnw;
        hnw = (s==0) ? bufA : ((hid==bufA) ? bufB : bufA);
    }
    final_kernel<<<ROWS,256>>>(hid, g2, b2, out);
}